// round 8
// baseline (speedup 1.0000x reference)
#include <cuda_runtime.h>
#include <cstdint>

// Problem dims (fixed)
#define TOK   8192      // B*N
#define DIM   1024      // D
#define NCB   64        // C codebooks
#define KD    16        // K
#define NP    64        // P keys
#define MV    128       // M
#define NR    8         // R
#define NPROJ 2048      // 2 branches * C*K

// 64 MB scratch for projections: proj[t][n], n = branch*1024 + c*16 + k
__device__ float g_proj[(size_t)TOK * NPROJ];

// ===========================================================================
// Kernel 1: 3xTF32 GEMM via mma.sync.m16n8k8 (layout verified in R7).
// proj precision here only gates argmin via the refine threshold below.
// ===========================================================================
#define BM 128
#define BN 128
#define BK 16
#define PSTR 20                 // padded row stride (floats)
#define TS (128 * PSTR)         // floats per tile buffer (2560)
#define GEMM_SMEM (2 * 4 * TS * 4)   // 81920 B

__device__ __forceinline__ uint32_t f2tf32(float x) {
    uint32_t r;
    asm("cvt.rna.tf32.f32 %0, %1;" : "=r"(r) : "f"(x));
    return r;
}

__device__ __forceinline__ void split4(float4 v, float4& h, float4& l) {
    h.x = __uint_as_float(f2tf32(v.x));
    h.y = __uint_as_float(f2tf32(v.y));
    h.z = __uint_as_float(f2tf32(v.z));
    h.w = __uint_as_float(f2tf32(v.w));
    l.x = __uint_as_float(f2tf32(v.x - h.x));
    l.y = __uint_as_float(f2tf32(v.y - h.y));
    l.z = __uint_as_float(f2tf32(v.z - h.z));
    l.w = __uint_as_float(f2tf32(v.w - h.w));
}

__device__ __forceinline__ void mma8(float* c, const uint32_t* a, const uint32_t* b) {
    asm volatile(
        "mma.sync.aligned.m16n8k8.row.col.f32.tf32.tf32.f32 "
        "{%0,%1,%2,%3}, {%4,%5,%6,%7}, {%8,%9}, {%0,%1,%2,%3};"
        : "+f"(c[0]), "+f"(c[1]), "+f"(c[2]), "+f"(c[3])
        : "r"(a[0]), "r"(a[1]), "r"(a[2]), "r"(a[3]), "r"(b[0]), "r"(b[1]));
}

__global__ __launch_bounds__(256, 1) void proj_gemm_mma(
    const float* __restrict__ X,
    const float* __restrict__ WA,
    const float* __restrict__ WB,
    float* __restrict__ out)
{
    extern __shared__ float sm[];
    const int tid  = threadIdx.x;
    const int warp = tid >> 5;
    const int lane = tid & 31;
    const int g    = lane >> 2;     // groupID
    const int tg   = lane & 3;      // threadID_in_group
    const int wm   = warp & 3;      // warp row  (4 x 32 rows)
    const int wn   = warp >> 2;     // warp col  (2 x 64 cols)

    const int n0 = blockIdx.x * BN;
    const int t0 = blockIdx.y * BM;
    const float* __restrict__ Wbase = (n0 < 1024) ? (WA + (size_t)n0 * DIM)
                                                  : (WB + (size_t)(n0 - 1024) * DIM);

    const int rowL = tid >> 2;
    const int c4   = tid & 3;
    const float* aSrc0 = X     + (size_t)(t0 + rowL) * DIM + c4 * 4;
    const float* aSrc1 = aSrc0 + (size_t)64 * DIM;
    const float* bSrc0 = Wbase + (size_t)rowL        * DIM + c4 * 4;
    const float* bSrc1 = bSrc0 + (size_t)64 * DIM;
    const int sOff0 = rowL * PSTR + c4 * 4;
    const int sOff1 = (rowL + 64) * PSTR + c4 * 4;

    float acc[2][8][4];
    #pragma unroll
    for (int mi = 0; mi < 2; mi++)
        #pragma unroll
        for (int ni = 0; ni < 8; ni++)
            #pragma unroll
            for (int q = 0; q < 4; q++) acc[mi][ni][q] = 0.f;

    float4 a0 = *(const float4*)(aSrc0);
    float4 a1 = *(const float4*)(aSrc1);
    float4 b0 = *(const float4*)(bSrc0);
    float4 b1 = *(const float4*)(bSrc1);

    const int NCHUNK_G = DIM / BK;   // 64
    for (int ch = 0; ch < NCHUNK_G; ch++) {
        float* AH = sm + ((ch & 1) * 4 + 0) * TS;
        float* AL = sm + ((ch & 1) * 4 + 1) * TS;
        float* BH = sm + ((ch & 1) * 4 + 2) * TS;
        float* BL = sm + ((ch & 1) * 4 + 3) * TS;

        {
            float4 h, l;
            split4(a0, h, l); *(float4*)(AH + sOff0) = h; *(float4*)(AL + sOff0) = l;
            split4(a1, h, l); *(float4*)(AH + sOff1) = h; *(float4*)(AL + sOff1) = l;
            split4(b0, h, l); *(float4*)(BH + sOff0) = h; *(float4*)(BL + sOff0) = l;
            split4(b1, h, l); *(float4*)(BH + sOff1) = h; *(float4*)(BL + sOff1) = l;
        }
        __syncthreads();

        if (ch < NCHUNK_G - 1) {
            const int k1 = (ch + 1) * BK;
            a0 = *(const float4*)(aSrc0 + k1);
            a1 = *(const float4*)(aSrc1 + k1);
            b0 = *(const float4*)(bSrc0 + k1);
            b1 = *(const float4*)(bSrc1 + k1);
        }

        #pragma unroll
        for (int kk = 0; kk < 2; kk++) {
            const int kc = kk * 8 + tg;

            uint32_t ah[2][4], al[2][4];
            #pragma unroll
            for (int mi = 0; mi < 2; mi++) {
                const int r0 = (wm * 32 + mi * 16 + g) * PSTR;
                ah[mi][0] = __float_as_uint(AH[r0 + kc]);
                ah[mi][1] = __float_as_uint(AH[r0 + 8 * PSTR + kc]);
                ah[mi][2] = __float_as_uint(AH[r0 + kc + 4]);
                ah[mi][3] = __float_as_uint(AH[r0 + 8 * PSTR + kc + 4]);
                al[mi][0] = __float_as_uint(AL[r0 + kc]);
                al[mi][1] = __float_as_uint(AL[r0 + 8 * PSTR + kc]);
                al[mi][2] = __float_as_uint(AL[r0 + kc + 4]);
                al[mi][3] = __float_as_uint(AL[r0 + 8 * PSTR + kc + 4]);
            }
            uint32_t bh[8][2], bl[8][2];
            #pragma unroll
            for (int ni = 0; ni < 8; ni++) {
                const int nb = (wn * 64 + ni * 8 + g) * PSTR;
                bh[ni][0] = __float_as_uint(BH[nb + kc]);
                bh[ni][1] = __float_as_uint(BH[nb + kc + 4]);
                bl[ni][0] = __float_as_uint(BL[nb + kc]);
                bl[ni][1] = __float_as_uint(BL[nb + kc + 4]);
            }

            #pragma unroll
            for (int mi = 0; mi < 2; mi++)
                #pragma unroll
                for (int ni = 0; ni < 8; ni++)
                    mma8(acc[mi][ni], ah[mi], bh[ni]);   // hh
            #pragma unroll
            for (int mi = 0; mi < 2; mi++)
                #pragma unroll
                for (int ni = 0; ni < 8; ni++)
                    mma8(acc[mi][ni], ah[mi], bl[ni]);   // hl
            #pragma unroll
            for (int mi = 0; mi < 2; mi++)
                #pragma unroll
                for (int ni = 0; ni < 8; ni++)
                    mma8(acc[mi][ni], al[mi], bh[ni]);   // lh
        }
    }

    #pragma unroll
    for (int mi = 0; mi < 2; mi++) {
        const int row = t0 + wm * 32 + mi * 16 + g;
        #pragma unroll
        for (int ni = 0; ni < 8; ni++) {
            const int col = n0 + wn * 64 + ni * 8 + tg * 2;
            *(float2*)(out + (size_t)row * NPROJ + col)
                = make_float2(acc[mi][ni][0], acc[mi][ni][1]);
            *(float2*)(out + (size_t)(row + 8) * NPROJ + col)
                = make_float2(acc[mi][ni][2], acc[mi][ni][3]);
        }
    }
}

// ---------------------------------------------------------------------------
// Kernel 2: fused argmin + gather-dot + output, with margin-gated fp32 refine.
// If the two best cheap scores are closer than REFINE_TH, recompute this
// codebook's 16-dim projection in exact fp32 and redo the argmin.
// ---------------------------------------------------------------------------
#define GTOK 8
#define FUSE_SMEM (GTOK * NPROJ * 4)   // 64 KB dynamic
#define REFINE_TH 0.05f

__device__ __forceinline__ unsigned ord_f32(float f) {
    unsigned b = __float_as_uint(f);
    return (b & 0x80000000u) ? ~b : (b | 0x80000000u);  // monotonic map
}

__global__ __launch_bounds__(256) void fuse_kernel(
    const float* __restrict__ x,
    const float* __restrict__ proj,
    const float* __restrict__ W_A_, const float* __restrict__ W_B_,
    const float* __restrict__ emb_A, const float* __restrict__ vals_A,
    const float* __restrict__ emb_B, const float* __restrict__ vals_B,
    float* __restrict__ out)
{
    extern __shared__ float proj_s[];            // GTOK*2048 floats
    __shared__ float sA[GTOK * NCB];
    __shared__ float tb[GTOK * NR];
    __shared__ int   idxA[GTOK * NCB];
    __shared__ int   idxB[GTOK * NCB];

    const int tid  = threadIdx.x;
    const int warp = tid >> 5;
    const int lane = tid & 31;
    const int tok0 = blockIdx.x * GTOK;

    // ---- stage proj via cp.async ----
    {
        const float* src = proj + (size_t)tok0 * NPROJ;
        unsigned sdst = (unsigned)__cvta_generic_to_shared(proj_s);
        #pragma unroll
        for (int i = tid; i < GTOK * NPROJ / 4; i += 256) {
            asm volatile("cp.async.cg.shared.global [%0], [%1], 16;"
                         :: "r"(sdst + i * 16), "l"(src + i * 4));
        }
        asm volatile("cp.async.commit_group;");
        asm volatile("cp.async.wait_group 0;");
    }
    __syncthreads();

    // ---- distance + argmin: 128 (branch, codebook) pairs over 8 warps ----
    for (int pair = warp; pair < 2 * NCB; pair += 8) {
        const int br = pair >> 6;
        const int c  = pair & 63;
        const float* emb = br ? emb_B : emb_A;
        float e0[KD], e1[KD];
        {
            const float4* r0 = (const float4*)(emb + ((size_t)c * NP + lane) * KD);
            const float4* r1 = r0 + 32 * KD / 4;
            #pragma unroll
            for (int q = 0; q < 4; q++) {
                float4 v0 = __ldg(r0 + q), v1 = __ldg(r1 + q);
                e0[q*4+0]=v0.x; e0[q*4+1]=v0.y; e0[q*4+2]=v0.z; e0[q*4+3]=v0.w;
                e1[q*4+0]=v1.x; e1[q*4+1]=v1.y; e1[q*4+2]=v1.z; e1[q*4+3]=v1.w;
            }
        }
        float ee0 = 0.f, ee1 = 0.f;
        #pragma unroll
        for (int k = 0; k < KD; k++) { ee0 = fmaf(e0[k], e0[k], ee0); ee1 = fmaf(e1[k], e1[k], ee1); }

        #pragma unroll
        for (int g2 = 0; g2 < GTOK; g2++) {
            const float4* pr = (const float4*)(proj_s + g2 * NPROJ + br * 1024 + c * KD);
            float p[KD];
            #pragma unroll
            for (int q = 0; q < 4; q++) {
                float4 v = pr[q];   // broadcast LDS.128
                p[q*4+0]=v.x; p[q*4+1]=v.y; p[q*4+2]=v.z; p[q*4+3]=v.w;
            }
            float pp = 0.f, d0 = 0.f, d1 = 0.f;
            #pragma unroll
            for (int k = 0; k < KD; k++) {
                pp = fmaf(p[k], p[k], pp);
                d0 = fmaf(p[k], e0[k], d0);
                d1 = fmaf(p[k], e1[k], d1);
            }
            float s0 = (pp - 2.0f * d0) + ee0;
            float s1 = (pp - 2.0f * d1) + ee1;

            // best index (packed lexicographic min: first-occurrence argmin)
            unsigned long long k0 = ((unsigned long long)ord_f32(s0) << 6) | (unsigned)lane;
            unsigned long long k1 = ((unsigned long long)ord_f32(s1) << 6) | (unsigned)(lane + 32);
            unsigned long long key = (k1 < k0) ? k1 : k0;
            // two-smallest-score reduce (for the refine gate)
            float lo = fminf(s0, s1), hi = fmaxf(s0, s1);
            #pragma unroll
            for (int off = 16; off > 0; off >>= 1) {
                unsigned long long o = __shfl_xor_sync(0xffffffffu, key, off);
                if (o < key) key = o;
                float olo = __shfl_xor_sync(0xffffffffu, lo, off);
                float ohi = __shfl_xor_sync(0xffffffffu, hi, off);
                float nlo = fminf(lo, olo);
                float nhi = fminf(fmaxf(lo, olo), fminf(hi, ohi));
                lo = nlo; hi = nhi;
            }

            if (hi - lo < REFINE_TH) {
                // exact fp32 refine: recompute 16-dim projection x . W[c]
                // lanes 2k,2k+1 jointly compute proj_k (interleaved float4s)
                const float* wrow = (br ? W_B_ : W_A_)
                                  + ((size_t)c * KD + (lane >> 1)) * DIM;
                const float* xrow = x + (size_t)(tok0 + g2) * DIM;
                float accp = 0.f;
                for (int d = (lane & 1) * 4; d < DIM; d += 8) {
                    float4 wv = __ldg((const float4*)(wrow + d));
                    float4 xv = *(const float4*)(xrow + d);
                    accp = fmaf(wv.x, xv.x, accp);
                    accp = fmaf(wv.y, xv.y, accp);
                    accp = fmaf(wv.z, xv.z, accp);
                    accp = fmaf(wv.w, xv.w, accp);
                }
                accp += __shfl_xor_sync(0xffffffffu, accp, 1);
                float pr2[KD];
                #pragma unroll
                for (int k = 0; k < KD; k++)
                    pr2[k] = __shfl_sync(0xffffffffu, accp, k * 2);
                float pp2 = 0.f, d0r = 0.f, d1r = 0.f;
                #pragma unroll
                for (int k = 0; k < KD; k++) {
                    pp2 = fmaf(pr2[k], pr2[k], pp2);
                    d0r = fmaf(pr2[k], e0[k], d0r);
                    d1r = fmaf(pr2[k], e1[k], d1r);
                }
                float r0s = (pp2 - 2.0f * d0r) + ee0;
                float r1s = (pp2 - 2.0f * d1r) + ee1;
                unsigned long long rk0 = ((unsigned long long)ord_f32(r0s) << 6) | (unsigned)lane;
                unsigned long long rk1 = ((unsigned long long)ord_f32(r1s) << 6) | (unsigned)(lane + 32);
                key = (rk1 < rk0) ? rk1 : rk0;
                #pragma unroll
                for (int off = 16; off > 0; off >>= 1) {
                    unsigned long long o = __shfl_xor_sync(0xffffffffu, key, off);
                    if (o < key) key = o;
                }
            }

            if (lane == 0) (br ? idxB : idxA)[g2 * NCB + c] = (int)(key & 63u);
        }
    }
    __syncthreads();

    // ---- sA: warp per (token, chunk); x-chunk in regs, 8x reuse over c ----
    for (int task = warp; task < GTOK * 8; task += 8) {
        const int g2 = task >> 3, chunk = task & 7;
        float4 xr = *(const float4*)(x + (size_t)(tok0 + g2) * DIM + chunk * MV + lane * 4);
        float acc[8];
        #pragma unroll
        for (int ci = 0; ci < 8; ci++) {
            const int c = ci * 8 + chunk;
            const int id = idxA[g2 * NCB + c];
            float4 vr = __ldg((const float4*)(vals_A + ((size_t)c * NP + id) * MV) + lane);
            acc[ci] = xr.x*vr.x + xr.y*vr.y + xr.z*vr.z + xr.w*vr.w;
        }
        #pragma unroll
        for (int off = 16; off > 0; off >>= 1)
            #pragma unroll
            for (int ci = 0; ci < 8; ci++)
                acc[ci] += __shfl_xor_sync(0xffffffffu, acc[ci], off);
        if (lane == 0) {
            #pragma unroll
            for (int ci = 0; ci < 8; ci++)
                sA[g2 * NCB + ci * 8 + chunk] = acc[ci];
        }
    }
    __syncthreads();

    // ---- t[g][r] = sum of 8 consecutive s ----
    if (tid < GTOK * NR) {
        const int g2 = tid >> 3, r = tid & 7;
        float acc = 0.f;
        #pragma unroll
        for (int i = 0; i < 8; i++) acc += sA[g2 * NCB + r * 8 + i];
        tb[g2 * NR + r] = acc;
    }
    __syncthreads();

    // ---- out[token][h*128+m] = sum_r t[r] * vals_B[8r+h, idxB[8r+h], m] ----
    for (int g2 = 0; g2 < GTOK; g2++) {
        float tr[NR];
        #pragma unroll
        for (int r = 0; r < NR; r++) tr[r] = tb[g2 * NR + r];
        float* orow = out + (size_t)(tok0 + g2) * DIM;
        #pragma unroll
        for (int j = 0; j < 4; j++) {
            const int d = tid + 256 * j;
            const int h = d >> 7, m = d & 127;
            float acc = 0.f;
            #pragma unroll
            for (int r = 0; r < NR; r++) {
                const int c = 8 * r + h;
                acc = fmaf(tr[r],
                           __ldg(vals_B + ((size_t)c * NP + idxB[g2 * NCB + c]) * MV + m),
                           acc);
            }
            orow[d] = acc;
        }
    }
}

// ---------------------------------------------------------------------------
extern "C" void kernel_launch(void* const* d_in, const int* in_sizes, int n_in,
                              void* d_out, int out_size)
{
    (void)in_sizes; (void)n_in; (void)out_size;
    const float* x      = (const float*)d_in[0];
    const float* W_A    = (const float*)d_in[1];
    const float* emb_A  = (const float*)d_in[2];
    const float* vals_A = (const float*)d_in[3];
    const float* W_B    = (const float*)d_in[4];
    const float* emb_B  = (const float*)d_in[5];
    const float* vals_B = (const float*)d_in[6];
    float* out = (float*)d_out;

    float* proj;
    cudaGetSymbolAddress((void**)&proj, g_proj);

    static bool attr_set = false;
    if (!attr_set) {
        cudaFuncSetAttribute(proj_gemm_mma,
                             cudaFuncAttributeMaxDynamicSharedMemorySize, GEMM_SMEM);
        cudaFuncSetAttribute(fuse_kernel,
                             cudaFuncAttributeMaxDynamicSharedMemorySize, FUSE_SMEM);
        attr_set = true;
    }

    dim3 gg(NPROJ / BN, TOK / BM);   // (16, 64)
    proj_gemm_mma<<<gg, 256, GEMM_SMEM>>>(x, W_A, W_B, proj);
    fuse_kernel<<<TOK / GTOK, 256, FUSE_SMEM>>>(x, proj, W_A, W_B,
                                                emb_A, vals_A, emb_B, vals_B, out);
}

// round 10
// speedup vs baseline: 1.2585x; 1.2585x over previous
#include <cuda_runtime.h>
#include <cstdint>

// Problem dims (fixed)
#define TOK   8192      // B*N
#define DIM   1024      // D
#define NCB   64        // C codebooks
#define KD    16        // K
#define NP    64        // P keys
#define MV    128       // M
#define NR    8         // R
#define NPROJ 2048      // 2 branches * C*K

// 64 MB scratch for projections: proj[t][n], n = branch*1024 + c*16 + k
__device__ float g_proj[(size_t)TOK * NPROJ];

// ===========================================================================
// Kernel 1: 3xTF32 GEMM via mma.sync.m16n8k8 (verified R7/R8; 584 us).
// ===========================================================================
#define BM 128
#define BN 128
#define BK 16
#define PSTR 20                 // padded row stride (floats)
#define TS (128 * PSTR)         // floats per tile buffer (2560)
#define GEMM_SMEM (2 * 4 * TS * 4)   // 81920 B

__device__ __forceinline__ uint32_t f2tf32(float x) {
    uint32_t r;
    asm("cvt.rna.tf32.f32 %0, %1;" : "=r"(r) : "f"(x));
    return r;
}

__device__ __forceinline__ void split4(float4 v, float4& h, float4& l) {
    h.x = __uint_as_float(f2tf32(v.x));
    h.y = __uint_as_float(f2tf32(v.y));
    h.z = __uint_as_float(f2tf32(v.z));
    h.w = __uint_as_float(f2tf32(v.w));
    l.x = __uint_as_float(f2tf32(v.x - h.x));
    l.y = __uint_as_float(f2tf32(v.y - h.y));
    l.z = __uint_as_float(f2tf32(v.z - h.z));
    l.w = __uint_as_float(f2tf32(v.w - h.w));
}

__device__ __forceinline__ void mma8(float* c, const uint32_t* a, const uint32_t* b) {
    asm volatile(
        "mma.sync.aligned.m16n8k8.row.col.f32.tf32.tf32.f32 "
        "{%0,%1,%2,%3}, {%4,%5,%6,%7}, {%8,%9}, {%0,%1,%2,%3};"
        : "+f"(c[0]), "+f"(c[1]), "+f"(c[2]), "+f"(c[3])
        : "r"(a[0]), "r"(a[1]), "r"(a[2]), "r"(a[3]), "r"(b[0]), "r"(b[1]));
}

__global__ __launch_bounds__(256, 1) void proj_gemm_mma(
    const float* __restrict__ X,
    const float* __restrict__ WA,
    const float* __restrict__ WB,
    float* __restrict__ out)
{
    extern __shared__ float sm[];
    const int tid  = threadIdx.x;
    const int warp = tid >> 5;
    const int lane = tid & 31;
    const int g    = lane >> 2;     // groupID
    const int tg   = lane & 3;      // threadID_in_group
    const int wm   = warp & 3;      // warp row  (4 x 32 rows)
    const int wn   = warp >> 2;     // warp col  (2 x 64 cols)

    const int n0 = blockIdx.x * BN;
    const int t0 = blockIdx.y * BM;
    const float* __restrict__ Wbase = (n0 < 1024) ? (WA + (size_t)n0 * DIM)
                                                  : (WB + (size_t)(n0 - 1024) * DIM);

    const int rowL = tid >> 2;
    const int c4   = tid & 3;
    const float* aSrc0 = X     + (size_t)(t0 + rowL) * DIM + c4 * 4;
    const float* aSrc1 = aSrc0 + (size_t)64 * DIM;
    const float* bSrc0 = Wbase + (size_t)rowL        * DIM + c4 * 4;
    const float* bSrc1 = bSrc0 + (size_t)64 * DIM;
    const int sOff0 = rowL * PSTR + c4 * 4;
    const int sOff1 = (rowL + 64) * PSTR + c4 * 4;

    float acc[2][8][4];
    #pragma unroll
    for (int mi = 0; mi < 2; mi++)
        #pragma unroll
        for (int ni = 0; ni < 8; ni++)
            #pragma unroll
            for (int q = 0; q < 4; q++) acc[mi][ni][q] = 0.f;

    float4 a0 = *(const float4*)(aSrc0);
    float4 a1 = *(const float4*)(aSrc1);
    float4 b0 = *(const float4*)(bSrc0);
    float4 b1 = *(const float4*)(bSrc1);

    const int NCHUNK_G = DIM / BK;   // 64
    for (int ch = 0; ch < NCHUNK_G; ch++) {
        float* AH = sm + ((ch & 1) * 4 + 0) * TS;
        float* AL = sm + ((ch & 1) * 4 + 1) * TS;
        float* BH = sm + ((ch & 1) * 4 + 2) * TS;
        float* BL = sm + ((ch & 1) * 4 + 3) * TS;

        {
            float4 h, l;
            split4(a0, h, l); *(float4*)(AH + sOff0) = h; *(float4*)(AL + sOff0) = l;
            split4(a1, h, l); *(float4*)(AH + sOff1) = h; *(float4*)(AL + sOff1) = l;
            split4(b0, h, l); *(float4*)(BH + sOff0) = h; *(float4*)(BL + sOff0) = l;
            split4(b1, h, l); *(float4*)(BH + sOff1) = h; *(float4*)(BL + sOff1) = l;
        }
        __syncthreads();

        if (ch < NCHUNK_G - 1) {
            const int k1 = (ch + 1) * BK;
            a0 = *(const float4*)(aSrc0 + k1);
            a1 = *(const float4*)(aSrc1 + k1);
            b0 = *(const float4*)(bSrc0 + k1);
            b1 = *(const float4*)(bSrc1 + k1);
        }

        #pragma unroll
        for (int kk = 0; kk < 2; kk++) {
            const int kc = kk * 8 + tg;

            uint32_t ah[2][4], al[2][4];
            #pragma unroll
            for (int mi = 0; mi < 2; mi++) {
                const int r0 = (wm * 32 + mi * 16 + g) * PSTR;
                ah[mi][0] = __float_as_uint(AH[r0 + kc]);
                ah[mi][1] = __float_as_uint(AH[r0 + 8 * PSTR + kc]);
                ah[mi][2] = __float_as_uint(AH[r0 + kc + 4]);
                ah[mi][3] = __float_as_uint(AH[r0 + 8 * PSTR + kc + 4]);
                al[mi][0] = __float_as_uint(AL[r0 + kc]);
                al[mi][1] = __float_as_uint(AL[r0 + 8 * PSTR + kc]);
                al[mi][2] = __float_as_uint(AL[r0 + kc + 4]);
                al[mi][3] = __float_as_uint(AL[r0 + 8 * PSTR + kc + 4]);
            }
            uint32_t bh[8][2], bl[8][2];
            #pragma unroll
            for (int ni = 0; ni < 8; ni++) {
                const int nb = (wn * 64 + ni * 8 + g) * PSTR;
                bh[ni][0] = __float_as_uint(BH[nb + kc]);
                bh[ni][1] = __float_as_uint(BH[nb + kc + 4]);
                bl[ni][0] = __float_as_uint(BL[nb + kc]);
                bl[ni][1] = __float_as_uint(BL[nb + kc + 4]);
            }

            #pragma unroll
            for (int mi = 0; mi < 2; mi++)
                #pragma unroll
                for (int ni = 0; ni < 8; ni++)
                    mma8(acc[mi][ni], ah[mi], bh[ni]);   // hh
            #pragma unroll
            for (int mi = 0; mi < 2; mi++)
                #pragma unroll
                for (int ni = 0; ni < 8; ni++)
                    mma8(acc[mi][ni], ah[mi], bl[ni]);   // hl
            #pragma unroll
            for (int mi = 0; mi < 2; mi++)
                #pragma unroll
                for (int ni = 0; ni < 8; ni++)
                    mma8(acc[mi][ni], al[mi], bh[ni]);   // lh
        }
    }

    #pragma unroll
    for (int mi = 0; mi < 2; mi++) {
        const int row = t0 + wm * 32 + mi * 16 + g;
        #pragma unroll
        for (int ni = 0; ni < 8; ni++) {
            const int col = n0 + wn * 64 + ni * 8 + tg * 2;
            *(float2*)(out + (size_t)row * NPROJ + col)
                = make_float2(acc[mi][ni][0], acc[mi][ni][1]);
            *(float2*)(out + (size_t)(row + 8) * NPROJ + col)
                = make_float2(acc[mi][ni][2], acc[mi][ni][3]);
        }
    }
}

// ---------------------------------------------------------------------------
// Kernel 2: fused argmin + gather-dot + output, margin-gated fp32 refine.
// Gate: ballot of "any non-winner score within REFINE_TH of the min"
// (min score recovered from the reduced key's ord bits — no extra reduce).
// ---------------------------------------------------------------------------
#define GTOK 8
#define FUSE_SMEM (GTOK * NPROJ * 4)   // 64 KB dynamic
#define REFINE_TH 0.01f

__device__ __forceinline__ unsigned ord_f32(float f) {
    unsigned b = __float_as_uint(f);
    return (b & 0x80000000u) ? ~b : (b | 0x80000000u);  // monotonic map
}

__device__ __forceinline__ float inv_ord(unsigned u) {
    unsigned b = (u & 0x80000000u) ? (u ^ 0x80000000u) : ~u;
    return __uint_as_float(b);
}

__global__ __launch_bounds__(256) void fuse_kernel(
    const float* __restrict__ x,
    const float* __restrict__ proj,
    const float* __restrict__ W_A_, const float* __restrict__ W_B_,
    const float* __restrict__ emb_A, const float* __restrict__ vals_A,
    const float* __restrict__ emb_B, const float* __restrict__ vals_B,
    float* __restrict__ out)
{
    extern __shared__ float proj_s[];            // GTOK*2048 floats
    __shared__ float sA[GTOK * NCB];
    __shared__ float tb[GTOK * NR];
    __shared__ int   idxA[GTOK * NCB];
    __shared__ int   idxB[GTOK * NCB];

    const int tid  = threadIdx.x;
    const int warp = tid >> 5;
    const int lane = tid & 31;
    const int tok0 = blockIdx.x * GTOK;

    // ---- stage proj via cp.async ----
    {
        const float* src = proj + (size_t)tok0 * NPROJ;
        unsigned sdst = (unsigned)__cvta_generic_to_shared(proj_s);
        #pragma unroll
        for (int i = tid; i < GTOK * NPROJ / 4; i += 256) {
            asm volatile("cp.async.cg.shared.global [%0], [%1], 16;"
                         :: "r"(sdst + i * 16), "l"(src + i * 4));
        }
        asm volatile("cp.async.commit_group;");
        asm volatile("cp.async.wait_group 0;");
    }
    __syncthreads();

    // ---- distance + argmin: 128 (branch, codebook) pairs over 8 warps ----
    for (int pair = warp; pair < 2 * NCB; pair += 8) {
        const int br = pair >> 6;
        const int c  = pair & 63;
        const float* emb = br ? emb_B : emb_A;
        float e0[KD], e1[KD];
        {
            const float4* r0 = (const float4*)(emb + ((size_t)c * NP + lane) * KD);
            const float4* r1 = r0 + 32 * KD / 4;
            #pragma unroll
            for (int q = 0; q < 4; q++) {
                float4 v0 = __ldg(r0 + q), v1 = __ldg(r1 + q);
                e0[q*4+0]=v0.x; e0[q*4+1]=v0.y; e0[q*4+2]=v0.z; e0[q*4+3]=v0.w;
                e1[q*4+0]=v1.x; e1[q*4+1]=v1.y; e1[q*4+2]=v1.z; e1[q*4+3]=v1.w;
            }
        }
        float ee0 = 0.f, ee1 = 0.f;
        #pragma unroll
        for (int k = 0; k < KD; k++) { ee0 = fmaf(e0[k], e0[k], ee0); ee1 = fmaf(e1[k], e1[k], ee1); }

        #pragma unroll
        for (int g2 = 0; g2 < GTOK; g2++) {
            const float4* pr = (const float4*)(proj_s + g2 * NPROJ + br * 1024 + c * KD);
            float p[KD];
            #pragma unroll
            for (int q = 0; q < 4; q++) {
                float4 v = pr[q];   // broadcast LDS.128
                p[q*4+0]=v.x; p[q*4+1]=v.y; p[q*4+2]=v.z; p[q*4+3]=v.w;
            }
            float pp = 0.f, d0 = 0.f, d1 = 0.f;
            #pragma unroll
            for (int k = 0; k < KD; k++) {
                pp = fmaf(p[k], p[k], pp);
                d0 = fmaf(p[k], e0[k], d0);
                d1 = fmaf(p[k], e1[k], d1);
            }
            float s0 = (pp - 2.0f * d0) + ee0;
            float s1 = (pp - 2.0f * d1) + ee1;

            // packed lexicographic min -> first-occurrence argmin
            unsigned long long k0 = ((unsigned long long)ord_f32(s0) << 6) | (unsigned)lane;
            unsigned long long k1 = ((unsigned long long)ord_f32(s1) << 6) | (unsigned)(lane + 32);
            unsigned long long key = (k1 < k0) ? k1 : k0;
            #pragma unroll
            for (int off = 16; off > 0; off >>= 1) {
                unsigned long long o = __shfl_xor_sync(0xffffffffu, key, off);
                if (o < key) key = o;
            }

            // gate: any non-winner score within TH of the min?
            const float smin = inv_ord((unsigned)(key >> 6));
            const int winner = (int)(key & 63u);
            bool c0 = (s0 - smin < REFINE_TH) && (lane != winner);
            bool c1 = (s1 - smin < REFINE_TH) && (lane + 32 != winner);
            unsigned need = __ballot_sync(0xffffffffu, c0) | __ballot_sync(0xffffffffu, c1);

            if (need) {
                // exact fp32 refine: recompute 16-dim projection x . W[c]
                // lanes 2k,2k+1 jointly compute proj_k (interleaved float4s)
                const float* wrow = (br ? W_B_ : W_A_)
                                  + ((size_t)c * KD + (lane >> 1)) * DIM;
                const float* xrow = x + (size_t)(tok0 + g2) * DIM;
                float acc0 = 0.f, acc1 = 0.f;
                #pragma unroll 2
                for (int d = (lane & 1) * 4; d < DIM; d += 16) {
                    float4 wv = __ldg((const float4*)(wrow + d));
                    float4 xv = *(const float4*)(xrow + d);
                    float4 wv2 = __ldg((const float4*)(wrow + d + 8));
                    float4 xv2 = *(const float4*)(xrow + d + 8);
                    acc0 = fmaf(wv.x, xv.x, acc0);
                    acc0 = fmaf(wv.y, xv.y, acc0);
                    acc0 = fmaf(wv.z, xv.z, acc0);
                    acc0 = fmaf(wv.w, xv.w, acc0);
                    acc1 = fmaf(wv2.x, xv2.x, acc1);
                    acc1 = fmaf(wv2.y, xv2.y, acc1);
                    acc1 = fmaf(wv2.z, xv2.z, acc1);
                    acc1 = fmaf(wv2.w, xv2.w, acc1);
                }
                float accp = acc0 + acc1;
                accp += __shfl_xor_sync(0xffffffffu, accp, 1);
                float pr2[KD];
                #pragma unroll
                for (int k = 0; k < KD; k++)
                    pr2[k] = __shfl_sync(0xffffffffu, accp, k * 2);
                float pp2 = 0.f, d0r = 0.f, d1r = 0.f;
                #pragma unroll
                for (int k = 0; k < KD; k++) {
                    pp2 = fmaf(pr2[k], pr2[k], pp2);
                    d0r = fmaf(pr2[k], e0[k], d0r);
                    d1r = fmaf(pr2[k], e1[k], d1r);
                }
                float r0s = (pp2 - 2.0f * d0r) + ee0;
                float r1s = (pp2 - 2.0f * d1r) + ee1;
                unsigned long long rk0 = ((unsigned long long)ord_f32(r0s) << 6) | (unsigned)lane;
                unsigned long long rk1 = ((unsigned long long)ord_f32(r1s) << 6) | (unsigned)(lane + 32);
                key = (rk1 < rk0) ? rk1 : rk0;
                #pragma unroll
                for (int off = 16; off > 0; off >>= 1) {
                    unsigned long long o = __shfl_xor_sync(0xffffffffu, key, off);
                    if (o < key) key = o;
                }
            }

            if (lane == 0) (br ? idxB : idxA)[g2 * NCB + c] = (int)(key & 63u);
        }
    }
    __syncthreads();

    // ---- sA: warp per (token, chunk); x-chunk in regs, 8x reuse over c ----
    for (int task = warp; task < GTOK * 8; task += 8) {
        const int g2 = task >> 3, chunk = task & 7;
        float4 xr = *(const float4*)(x + (size_t)(tok0 + g2) * DIM + chunk * MV + lane * 4);
        float acc[8];
        #pragma unroll
        for (int ci = 0; ci < 8; ci++) {
            const int c = ci * 8 + chunk;
            const int id = idxA[g2 * NCB + c];
            float4 vr = __ldg((const float4*)(vals_A + ((size_t)c * NP + id) * MV) + lane);
            acc[ci] = xr.x*vr.x + xr.y*vr.y + xr.z*vr.z + xr.w*vr.w;
        }
        #pragma unroll
        for (int off = 16; off > 0; off >>= 1)
            #pragma unroll
            for (int ci = 0; ci < 8; ci++)
                acc[ci] += __shfl_xor_sync(0xffffffffu, acc[ci], off);
        if (lane == 0) {
            #pragma unroll
            for (int ci = 0; ci < 8; ci++)
                sA[g2 * NCB + ci * 8 + chunk] = acc[ci];
        }
    }
    __syncthreads();

    // ---- t[g][r] = sum of 8 consecutive s ----
    if (tid < GTOK * NR) {
        const int g2 = tid >> 3, r = tid & 7;
        float acc = 0.f;
        #pragma unroll
        for (int i = 0; i < 8; i++) acc += sA[g2 * NCB + r * 8 + i];
        tb[g2 * NR + r] = acc;
    }
    __syncthreads();

    // ---- out[token][h*128+m] = sum_r t[r] * vals_B[8r+h, idxB[8r+h], m] ----
    for (int g2 = 0; g2 < GTOK; g2++) {
        float tr[NR];
        #pragma unroll
        for (int r = 0; r < NR; r++) tr[r] = tb[g2 * NR + r];
        float* orow = out + (size_t)(tok0 + g2) * DIM;
        #pragma unroll
        for (int j = 0; j < 4; j++) {
            const int d = tid + 256 * j;
            const int h = d >> 7, m = d & 127;
            float acc = 0.f;
            #pragma unroll
            for (int r = 0; r < NR; r++) {
                const int c = 8 * r + h;
                acc = fmaf(tr[r],
                           __ldg(vals_B + ((size_t)c * NP + idxB[g2 * NCB + c]) * MV + m),
                           acc);
            }
            orow[d] = acc;
        }
    }
}

// ---------------------------------------------------------------------------
extern "C" void kernel_launch(void* const* d_in, const int* in_sizes, int n_in,
                              void* d_out, int out_size)
{
    (void)in_sizes; (void)n_in; (void)out_size;
    const float* x      = (const float*)d_in[0];
    const float* W_A    = (const float*)d_in[1];
    const float* emb_A  = (const float*)d_in[2];
    const float* vals_A = (const float*)d_in[3];
    const float* W_B    = (const float*)d_in[4];
    const float* emb_B  = (const float*)d_in[5];
    const float* vals_B = (const float*)d_in[6];
    float* out = (float*)d_out;

    float* proj;
    cudaGetSymbolAddress((void**)&proj, g_proj);

    static bool attr_set = false;
    if (!attr_set) {
        cudaFuncSetAttribute(proj_gemm_mma,
                             cudaFuncAttributeMaxDynamicSharedMemorySize, GEMM_SMEM);
        cudaFuncSetAttribute(fuse_kernel,
                             cudaFuncAttributeMaxDynamicSharedMemorySize, FUSE_SMEM);
        attr_set = true;
    }

    dim3 gg(NPROJ / BN, TOK / BM);   // (16, 64)
    proj_gemm_mma<<<gg, 256, GEMM_SMEM>>>(x, W_A, W_B, proj);
    fuse_kernel<<<TOK / GTOK, 256, FUSE_SMEM>>>(x, proj, W_A, W_B,
                                                emb_A, vals_A, emb_B, vals_B, out);
}

// round 12
// speedup vs baseline: 1.4366x; 1.1416x over previous
#include <cuda_runtime.h>
#include <cstdint>

// Problem dims (fixed)
#define TOK   8192      // B*N
#define DIM   1024      // D
#define NCB   64        // C codebooks
#define KD    16        // K
#define NP    64        // P keys
#define MV    128       // M
#define NR    8         // R
#define NPROJ 2048      // 2 branches * C*K

// 64 MB scratch for projections: proj[t][n], n = branch*1024 + c*16 + k
__device__ float g_proj[(size_t)TOK * NPROJ];

// ===========================================================================
// Kernel 1: 3xTF32 GEMM via mma.sync.m16n8k8 (verified R7/R8/R10).
// R11 change (re-bench): occupancy 1 -> 2 CTAs/SM (launch_bounds(256,2)).
// ===========================================================================
#define BM 128
#define BN 128
#define BK 16
#define PSTR 20                 // padded row stride (floats)
#define TS (128 * PSTR)         // floats per tile buffer (2560)
#define GEMM_SMEM (2 * 4 * TS * 4)   // 81920 B

__device__ __forceinline__ uint32_t f2tf32(float x) {
    uint32_t r;
    asm("cvt.rna.tf32.f32 %0, %1;" : "=r"(r) : "f"(x));
    return r;
}

__device__ __forceinline__ void split4(float4 v, float4& h, float4& l) {
    h.x = __uint_as_float(f2tf32(v.x));
    h.y = __uint_as_float(f2tf32(v.y));
    h.z = __uint_as_float(f2tf32(v.z));
    h.w = __uint_as_float(f2tf32(v.w));
    l.x = __uint_as_float(f2tf32(v.x - h.x));
    l.y = __uint_as_float(f2tf32(v.y - h.y));
    l.z = __uint_as_float(f2tf32(v.z - h.z));
    l.w = __uint_as_float(f2tf32(v.w - h.w));
}

__device__ __forceinline__ void mma8(float* c, const uint32_t* a, const uint32_t* b) {
    asm volatile(
        "mma.sync.aligned.m16n8k8.row.col.f32.tf32.tf32.f32 "
        "{%0,%1,%2,%3}, {%4,%5,%6,%7}, {%8,%9}, {%0,%1,%2,%3};"
        : "+f"(c[0]), "+f"(c[1]), "+f"(c[2]), "+f"(c[3])
        : "r"(a[0]), "r"(a[1]), "r"(a[2]), "r"(a[3]), "r"(b[0]), "r"(b[1]));
}

__global__ __launch_bounds__(256, 2) void proj_gemm_mma(
    const float* __restrict__ X,
    const float* __restrict__ WA,
    const float* __restrict__ WB,
    float* __restrict__ out)
{
    extern __shared__ float sm[];
    const int tid  = threadIdx.x;
    const int warp = tid >> 5;
    const int lane = tid & 31;
    const int g    = lane >> 2;     // groupID
    const int tg   = lane & 3;      // threadID_in_group
    const int wm   = warp & 3;      // warp row  (4 x 32 rows)
    const int wn   = warp >> 2;     // warp col  (2 x 64 cols)

    const int n0 = blockIdx.x * BN;
    const int t0 = blockIdx.y * BM;
    const float* __restrict__ Wbase = (n0 < 1024) ? (WA + (size_t)n0 * DIM)
                                                  : (WB + (size_t)(n0 - 1024) * DIM);

    const int rowL = tid >> 2;
    const int c4   = tid & 3;
    const float* aSrc0 = X     + (size_t)(t0 + rowL) * DIM + c4 * 4;
    const float* aSrc1 = aSrc0 + (size_t)64 * DIM;
    const float* bSrc0 = Wbase + (size_t)rowL        * DIM + c4 * 4;
    const float* bSrc1 = bSrc0 + (size_t)64 * DIM;
    const int sOff0 = rowL * PSTR + c4 * 4;
    const int sOff1 = (rowL + 64) * PSTR + c4 * 4;

    float acc[2][8][4];
    #pragma unroll
    for (int mi = 0; mi < 2; mi++)
        #pragma unroll
        for (int ni = 0; ni < 8; ni++)
            #pragma unroll
            for (int q = 0; q < 4; q++) acc[mi][ni][q] = 0.f;

    float4 a0 = *(const float4*)(aSrc0);
    float4 a1 = *(const float4*)(aSrc1);
    float4 b0 = *(const float4*)(bSrc0);
    float4 b1 = *(const float4*)(bSrc1);

    const int NCHUNK_G = DIM / BK;   // 64
    for (int ch = 0; ch < NCHUNK_G; ch++) {
        float* AH = sm + ((ch & 1) * 4 + 0) * TS;
        float* AL = sm + ((ch & 1) * 4 + 1) * TS;
        float* BH = sm + ((ch & 1) * 4 + 2) * TS;
        float* BL = sm + ((ch & 1) * 4 + 3) * TS;

        {
            float4 h, l;
            split4(a0, h, l); *(float4*)(AH + sOff0) = h; *(float4*)(AL + sOff0) = l;
            split4(a1, h, l); *(float4*)(AH + sOff1) = h; *(float4*)(AL + sOff1) = l;
            split4(b0, h, l); *(float4*)(BH + sOff0) = h; *(float4*)(BL + sOff0) = l;
            split4(b1, h, l); *(float4*)(BH + sOff1) = h; *(float4*)(BL + sOff1) = l;
        }
        __syncthreads();

        if (ch < NCHUNK_G - 1) {
            const int k1 = (ch + 1) * BK;
            a0 = *(const float4*)(aSrc0 + k1);
            a1 = *(const float4*)(aSrc1 + k1);
            b0 = *(const float4*)(bSrc0 + k1);
            b1 = *(const float4*)(bSrc1 + k1);
        }

        #pragma unroll
        for (int kk = 0; kk < 2; kk++) {
            const int kc = kk * 8 + tg;

            uint32_t ah[2][4], al[2][4];
            #pragma unroll
            for (int mi = 0; mi < 2; mi++) {
                const int r0 = (wm * 32 + mi * 16 + g) * PSTR;
                ah[mi][0] = __float_as_uint(AH[r0 + kc]);
                ah[mi][1] = __float_as_uint(AH[r0 + 8 * PSTR + kc]);
                ah[mi][2] = __float_as_uint(AH[r0 + kc + 4]);
                ah[mi][3] = __float_as_uint(AH[r0 + 8 * PSTR + kc + 4]);
                al[mi][0] = __float_as_uint(AL[r0 + kc]);
                al[mi][1] = __float_as_uint(AL[r0 + 8 * PSTR + kc]);
                al[mi][2] = __float_as_uint(AL[r0 + kc + 4]);
                al[mi][3] = __float_as_uint(AL[r0 + 8 * PSTR + kc + 4]);
            }
            uint32_t bh[8][2], bl[8][2];
            #pragma unroll
            for (int ni = 0; ni < 8; ni++) {
                const int nb = (wn * 64 + ni * 8 + g) * PSTR;
                bh[ni][0] = __float_as_uint(BH[nb + kc]);
                bh[ni][1] = __float_as_uint(BH[nb + kc + 4]);
                bl[ni][0] = __float_as_uint(BL[nb + kc]);
                bl[ni][1] = __float_as_uint(BL[nb + kc + 4]);
            }

            #pragma unroll
            for (int mi = 0; mi < 2; mi++)
                #pragma unroll
                for (int ni = 0; ni < 8; ni++)
                    mma8(acc[mi][ni], ah[mi], bh[ni]);   // hh
            #pragma unroll
            for (int mi = 0; mi < 2; mi++)
                #pragma unroll
                for (int ni = 0; ni < 8; ni++)
                    mma8(acc[mi][ni], ah[mi], bl[ni]);   // hl
            #pragma unroll
            for (int mi = 0; mi < 2; mi++)
                #pragma unroll
                for (int ni = 0; ni < 8; ni++)
                    mma8(acc[mi][ni], al[mi], bh[ni]);   // lh
        }
    }

    #pragma unroll
    for (int mi = 0; mi < 2; mi++) {
        const int row = t0 + wm * 32 + mi * 16 + g;
        #pragma unroll
        for (int ni = 0; ni < 8; ni++) {
            const int col = n0 + wn * 64 + ni * 8 + tg * 2;
            *(float2*)(out + (size_t)row * NPROJ + col)
                = make_float2(acc[mi][ni][0], acc[mi][ni][1]);
            *(float2*)(out + (size_t)(row + 8) * NPROJ + col)
                = make_float2(acc[mi][ni][2], acc[mi][ni][3]);
        }
    }
}

// ---------------------------------------------------------------------------
// Kernel 2: fused argmin + gather-dot + output, margin-gated fp32 refine.
// R11 change (re-bench): REFINE_TH 0.01 -> 0.002 (~200x the ~1e-5 score err).
// ---------------------------------------------------------------------------
#define GTOK 8
#define FUSE_SMEM (GTOK * NPROJ * 4)   // 64 KB dynamic
#define REFINE_TH 0.002f

__device__ __forceinline__ unsigned ord_f32(float f) {
    unsigned b = __float_as_uint(f);
    return (b & 0x80000000u) ? ~b : (b | 0x80000000u);  // monotonic map
}

__device__ __forceinline__ float inv_ord(unsigned u) {
    unsigned b = (u & 0x80000000u) ? (u ^ 0x80000000u) : ~u;
    return __uint_as_float(b);
}

__global__ __launch_bounds__(256) void fuse_kernel(
    const float* __restrict__ x,
    const float* __restrict__ proj,
    const float* __restrict__ W_A_, const float* __restrict__ W_B_,
    const float* __restrict__ emb_A, const float* __restrict__ vals_A,
    const float* __restrict__ emb_B, const float* __restrict__ vals_B,
    float* __restrict__ out)
{
    extern __shared__ float proj_s[];            // GTOK*2048 floats
    __shared__ float sA[GTOK * NCB];
    __shared__ float tb[GTOK * NR];
    __shared__ int   idxA[GTOK * NCB];
    __shared__ int   idxB[GTOK * NCB];

    const int tid  = threadIdx.x;
    const int warp = tid >> 5;
    const int lane = tid & 31;
    const int tok0 = blockIdx.x * GTOK;

    // ---- stage proj via cp.async ----
    {
        const float* src = proj + (size_t)tok0 * NPROJ;
        unsigned sdst = (unsigned)__cvta_generic_to_shared(proj_s);
        #pragma unroll
        for (int i = tid; i < GTOK * NPROJ / 4; i += 256) {
            asm volatile("cp.async.cg.shared.global [%0], [%1], 16;"
                         :: "r"(sdst + i * 16), "l"(src + i * 4));
        }
        asm volatile("cp.async.commit_group;");
        asm volatile("cp.async.wait_group 0;");
    }
    __syncthreads();

    // ---- distance + argmin: 128 (branch, codebook) pairs over 8 warps ----
    for (int pair = warp; pair < 2 * NCB; pair += 8) {
        const int br = pair >> 6;
        const int c  = pair & 63;
        const float* emb = br ? emb_B : emb_A;
        float e0[KD], e1[KD];
        {
            const float4* r0 = (const float4*)(emb + ((size_t)c * NP + lane) * KD);
            const float4* r1 = r0 + 32 * KD / 4;
            #pragma unroll
            for (int q = 0; q < 4; q++) {
                float4 v0 = __ldg(r0 + q), v1 = __ldg(r1 + q);
                e0[q*4+0]=v0.x; e0[q*4+1]=v0.y; e0[q*4+2]=v0.z; e0[q*4+3]=v0.w;
                e1[q*4+0]=v1.x; e1[q*4+1]=v1.y; e1[q*4+2]=v1.z; e1[q*4+3]=v1.w;
            }
        }
        float ee0 = 0.f, ee1 = 0.f;
        #pragma unroll
        for (int k = 0; k < KD; k++) { ee0 = fmaf(e0[k], e0[k], ee0); ee1 = fmaf(e1[k], e1[k], ee1); }

        #pragma unroll
        for (int g2 = 0; g2 < GTOK; g2++) {
            const float4* pr = (const float4*)(proj_s + g2 * NPROJ + br * 1024 + c * KD);
            float p[KD];
            #pragma unroll
            for (int q = 0; q < 4; q++) {
                float4 v = pr[q];   // broadcast LDS.128
                p[q*4+0]=v.x; p[q*4+1]=v.y; p[q*4+2]=v.z; p[q*4+3]=v.w;
            }
            float pp = 0.f, d0 = 0.f, d1 = 0.f;
            #pragma unroll
            for (int k = 0; k < KD; k++) {
                pp = fmaf(p[k], p[k], pp);
                d0 = fmaf(p[k], e0[k], d0);
                d1 = fmaf(p[k], e1[k], d1);
            }
            float s0 = (pp - 2.0f * d0) + ee0;
            float s1 = (pp - 2.0f * d1) + ee1;

            // packed lexicographic min -> first-occurrence argmin
            unsigned long long k0 = ((unsigned long long)ord_f32(s0) << 6) | (unsigned)lane;
            unsigned long long k1 = ((unsigned long long)ord_f32(s1) << 6) | (unsigned)(lane + 32);
            unsigned long long key = (k1 < k0) ? k1 : k0;
            #pragma unroll
            for (int off = 16; off > 0; off >>= 1) {
                unsigned long long o = __shfl_xor_sync(0xffffffffu, key, off);
                if (o < key) key = o;
            }

            // gate: any non-winner score within TH of the min?
            const float smin = inv_ord((unsigned)(key >> 6));
            const int winner = (int)(key & 63u);
            bool c0 = (s0 - smin < REFINE_TH) && (lane != winner);
            bool c1 = (s1 - smin < REFINE_TH) && (lane + 32 != winner);
            unsigned need = __ballot_sync(0xffffffffu, c0) | __ballot_sync(0xffffffffu, c1);

            if (need) {
                // exact fp32 refine: recompute 16-dim projection x . W[c]
                // lanes 2k,2k+1 jointly compute proj_k (interleaved float4s)
                const float* wrow = (br ? W_B_ : W_A_)
                                  + ((size_t)c * KD + (lane >> 1)) * DIM;
                const float* xrow = x + (size_t)(tok0 + g2) * DIM;
                float acc0 = 0.f, acc1 = 0.f;
                #pragma unroll 2
                for (int d = (lane & 1) * 4; d < DIM; d += 16) {
                    float4 wv = __ldg((const float4*)(wrow + d));
                    float4 xv = *(const float4*)(xrow + d);
                    float4 wv2 = __ldg((const float4*)(wrow + d + 8));
                    float4 xv2 = *(const float4*)(xrow + d + 8);
                    acc0 = fmaf(wv.x, xv.x, acc0);
                    acc0 = fmaf(wv.y, xv.y, acc0);
                    acc0 = fmaf(wv.z, xv.z, acc0);
                    acc0 = fmaf(wv.w, xv.w, acc0);
                    acc1 = fmaf(wv2.x, xv2.x, acc1);
                    acc1 = fmaf(wv2.y, xv2.y, acc1);
                    acc1 = fmaf(wv2.z, xv2.z, acc1);
                    acc1 = fmaf(wv2.w, xv2.w, acc1);
                }
                float accp = acc0 + acc1;
                accp += __shfl_xor_sync(0xffffffffu, accp, 1);
                float pr2[KD];
                #pragma unroll
                for (int k = 0; k < KD; k++)
                    pr2[k] = __shfl_sync(0xffffffffu, accp, k * 2);
                float pp2 = 0.f, d0r = 0.f, d1r = 0.f;
                #pragma unroll
                for (int k = 0; k < KD; k++) {
                    pp2 = fmaf(pr2[k], pr2[k], pp2);
                    d0r = fmaf(pr2[k], e0[k], d0r);
                    d1r = fmaf(pr2[k], e1[k], d1r);
                }
                float r0s = (pp2 - 2.0f * d0r) + ee0;
                float r1s = (pp2 - 2.0f * d1r) + ee1;
                unsigned long long rk0 = ((unsigned long long)ord_f32(r0s) << 6) | (unsigned)lane;
                unsigned long long rk1 = ((unsigned long long)ord_f32(r1s) << 6) | (unsigned)(lane + 32);
                key = (rk1 < rk0) ? rk1 : rk0;
                #pragma unroll
                for (int off = 16; off > 0; off >>= 1) {
                    unsigned long long o = __shfl_xor_sync(0xffffffffu, key, off);
                    if (o < key) key = o;
                }
            }

            if (lane == 0) (br ? idxB : idxA)[g2 * NCB + c] = (int)(key & 63u);
        }
    }
    __syncthreads();

    // ---- sA: warp per (token, chunk); x-chunk in regs, 8x reuse over c ----
    for (int task = warp; task < GTOK * 8; task += 8) {
        const int g2 = task >> 3, chunk = task & 7;
        float4 xr = *(const float4*)(x + (size_t)(tok0 + g2) * DIM + chunk * MV + lane * 4);
        float acc[8];
        #pragma unroll
        for (int ci = 0; ci < 8; ci++) {
            const int c = ci * 8 + chunk;
            const int id = idxA[g2 * NCB + c];
            float4 vr = __ldg((const float4*)(vals_A + ((size_t)c * NP + id) * MV) + lane);
            acc[ci] = xr.x*vr.x + xr.y*vr.y + xr.z*vr.z + xr.w*vr.w;
        }
        #pragma unroll
        for (int off = 16; off > 0; off >>= 1)
            #pragma unroll
            for (int ci = 0; ci < 8; ci++)
                acc[ci] += __shfl_xor_sync(0xffffffffu, acc[ci], off);
        if (lane == 0) {
            #pragma unroll
            for (int ci = 0; ci < 8; ci++)
                sA[g2 * NCB + ci * 8 + chunk] = acc[ci];
        }
    }
    __syncthreads();

    // ---- t[g][r] = sum of 8 consecutive s ----
    if (tid < GTOK * NR) {
        const int g2 = tid >> 3, r = tid & 7;
        float acc = 0.f;
        #pragma unroll
        for (int i = 0; i < 8; i++) acc += sA[g2 * NCB + r * 8 + i];
        tb[g2 * NR + r] = acc;
    }
    __syncthreads();

    // ---- out[token][h*128+m] = sum_r t[r] * vals_B[8r+h, idxB[8r+h], m] ----
    for (int g2 = 0; g2 < GTOK; g2++) {
        float tr[NR];
        #pragma unroll
        for (int r = 0; r < NR; r++) tr[r] = tb[g2 * NR + r];
        float* orow = out + (size_t)(tok0 + g2) * DIM;
        #pragma unroll
        for (int j = 0; j < 4; j++) {
            const int d = tid + 256 * j;
            const int h = d >> 7, m = d & 127;
            float acc = 0.f;
            #pragma unroll
            for (int r = 0; r < NR; r++) {
                const int c = 8 * r + h;
                acc = fmaf(tr[r],
                           __ldg(vals_B + ((size_t)c * NP + idxB[g2 * NCB + c]) * MV + m),
                           acc);
            }
            orow[d] = acc;
        }
    }
}

// ---------------------------------------------------------------------------
extern "C" void kernel_launch(void* const* d_in, const int* in_sizes, int n_in,
                              void* d_out, int out_size)
{
    (void)in_sizes; (void)n_in; (void)out_size;
    const float* x      = (const float*)d_in[0];
    const float* W_A    = (const float*)d_in[1];
    const float* emb_A  = (const float*)d_in[2];
    const float* vals_A = (const float*)d_in[3];
    const float* W_B    = (const float*)d_in[4];
    const float* emb_B  = (const float*)d_in[5];
    const float* vals_B = (const float*)d_in[6];
    float* out = (float*)d_out;

    float* proj;
    cudaGetSymbolAddress((void**)&proj, g_proj);

    static bool attr_set = false;
    if (!attr_set) {
        cudaFuncSetAttribute(proj_gemm_mma,
                             cudaFuncAttributeMaxDynamicSharedMemorySize, GEMM_SMEM);
        cudaFuncSetAttribute(fuse_kernel,
                             cudaFuncAttributeMaxDynamicSharedMemorySize, FUSE_SMEM);
        attr_set = true;
    }

    dim3 gg(NPROJ / BN, TOK / BM);   // (16, 64)
    proj_gemm_mma<<<gg, 256, GEMM_SMEM>>>(x, W_A, W_B, proj);
    fuse_kernel<<<TOK / GTOK, 256, FUSE_SMEM>>>(x, proj, W_A, W_B,
                                                emb_A, vals_A, emb_B, vals_B, out);
}